// round 11
// baseline (speedup 1.0000x reference)
#include <cuda_runtime.h>
#include <cstdint>
#include <mma.h>
#include <math.h>
#include <cuda_bf16.h>
#include <cuda_fp16.h>

using namespace nvcuda;

#define DM   1024
#define NB   4
#define SQ   4096

// Scratch (device globals: the sanctioned alloc-free workaround)
__device__ float g_q[(size_t)NB * SQ * DM];
__device__ float g_k[(size_t)NB * SQ * DM];
__device__ float g_v[(size_t)NB * SQ * DM];
__device__ float g_s[(size_t)NB * SQ * SQ];
__device__ __nv_bfloat16 g_xh[(size_t)NB * SQ * DM];
__device__ __nv_bfloat16 g_xl[(size_t)NB * SQ * DM];
__device__ __nv_bfloat16 g_wh[3][(size_t)DM * DM];
__device__ __nv_bfloat16 g_wl[3][(size_t)DM * DM];

__device__ __forceinline__ void cp_async16(void* dst_smem, const void* src_gmem)
{
    uint32_t d = (uint32_t)__cvta_generic_to_shared(dst_smem);
    asm volatile("cp.async.cg.shared.global [%0], [%1], 16;\n" :: "r"(d), "l"(src_gmem));
}
__device__ __forceinline__ void cp_commit() { asm volatile("cp.async.commit_group;\n" ::); }
__device__ __forceinline__ void cp_wait0()  { asm volatile("cp.async.wait_group 0;\n" ::); }
__device__ __forceinline__ void cp_wait1()  { asm volatile("cp.async.wait_group 1;\n" ::); }

// ===========================================================================
// Elementwise split: fp32 -> bf16 hi + bf16 lo.
// ===========================================================================
__global__ void __launch_bounds__(256) split_bf16(
    const float* __restrict__ in, __nv_bfloat16* __restrict__ h,
    __nv_bfloat16* __restrict__ l, int n)
{
    int idx = (blockIdx.x * 256 + threadIdx.x) * 4;
    if (idx >= n) return;
    float4 v = *(const float4*)&in[idx];
    __nv_bfloat16 h0 = __float2bfloat16_rn(v.x);
    __nv_bfloat16 h1 = __float2bfloat16_rn(v.y);
    __nv_bfloat16 h2 = __float2bfloat16_rn(v.z);
    __nv_bfloat16 h3 = __float2bfloat16_rn(v.w);
    __nv_bfloat16 l0 = __float2bfloat16_rn(v.x - __bfloat162float(h0));
    __nv_bfloat16 l1 = __float2bfloat16_rn(v.y - __bfloat162float(h1));
    __nv_bfloat16 l2 = __float2bfloat16_rn(v.z - __bfloat162float(h2));
    __nv_bfloat16 l3 = __float2bfloat16_rn(v.w - __bfloat162float(h3));
    ushort4 hv = { __bfloat16_as_ushort(h0), __bfloat16_as_ushort(h1),
                   __bfloat16_as_ushort(h2), __bfloat16_as_ushort(h3) };
    ushort4 lv = { __bfloat16_as_ushort(l0), __bfloat16_as_ushort(l1),
                   __bfloat16_as_ushort(l2), __bfloat16_as_ushort(l3) };
    *(ushort4*)&h[idx] = hv;
    *(ushort4*)&l[idx] = lv;
}

// ===========================================================================
// QKV: C(M,N) = (Ah+Al)(M,K) x (Bh+Bl)(N,K)^T, bf16 3-term, fp32 accum.
// Epilogue rounds C to the tf32 grid. 2-stage cp.async (unchanged from R8).
// ===========================================================================
__global__ void __launch_bounds__(256, 2) gemm_qkv_bf16(
    const __nv_bfloat16* __restrict__ Ah, const __nv_bfloat16* __restrict__ Al,
    const __nv_bfloat16* __restrict__ Bh, const __nv_bfloat16* __restrict__ Bl,
    float* __restrict__ C, int N, int K)
{
    constexpr int BM = 128, BN = 128, BK = 32, LD = BK + 16;  // bf16 elems
    extern __shared__ __align__(16) char smraw[];
    __nv_bfloat16* sAh = (__nv_bfloat16*)smraw;            // [2][BM][LD]
    __nv_bfloat16* sAl = sAh + 2 * BM * LD;
    __nv_bfloat16* sBh = sAl + 2 * BM * LD;                // [2][BN][LD]
    __nv_bfloat16* sBl = sBh + 2 * BN * LD;

    const int tm   = blockIdx.y * BM;
    const int tn   = blockIdx.x * BN;
    const int tid  = threadIdx.x;
    const int warp = tid >> 5;
    const int wm   = (warp >> 1) * 32;
    const int wn   = (warp & 1) * 64;

    wmma::fragment<wmma::accumulator, 16, 16, 16, float> acc[2][4];
#pragma unroll
    for (int i = 0; i < 2; i++)
#pragma unroll
        for (int j = 0; j < 4; j++) wmma::fill_fragment(acc[i][j], 0.0f);

    const int lr = tid >> 1;
    const int lc = (tid & 1) * 16;

    auto load_tile = [&](int buf, int kk) {
        long ga = (long)(tm + lr) * K + kk + lc;
        long gb = (long)(tn + lr) * K + kk + lc;
        int  sa = (buf * BM + lr) * LD + lc;
        int  sb = (buf * BN + lr) * LD + lc;
        cp_async16(&sAh[sa],     &Ah[ga]);
        cp_async16(&sAh[sa + 8], &Ah[ga + 8]);
        cp_async16(&sAl[sa],     &Al[ga]);
        cp_async16(&sAl[sa + 8], &Al[ga + 8]);
        cp_async16(&sBh[sb],     &Bh[gb]);
        cp_async16(&sBh[sb + 8], &Bh[gb + 8]);
        cp_async16(&sBl[sb],     &Bl[gb]);
        cp_async16(&sBl[sb + 8], &Bl[gb + 8]);
        cp_commit();
    };

    load_tile(0, 0);
    int buf = 0;
    for (int kk = 0; kk < K; kk += BK) {
        const bool has_next = (kk + BK) < K;
        if (has_next) {
            load_tile(buf ^ 1, kk + BK);
            cp_wait1();
        } else {
            cp_wait0();
        }
        __syncthreads();

#pragma unroll
        for (int ks = 0; ks < BK; ks += 16) {
            wmma::fragment<wmma::matrix_a, 16, 16, 16, __nv_bfloat16, wmma::row_major> ah[2], al[2];
            wmma::fragment<wmma::matrix_b, 16, 16, 16, __nv_bfloat16, wmma::col_major> bh[4], bl[4];
#pragma unroll
            for (int i = 0; i < 2; i++) {
                wmma::load_matrix_sync(ah[i], &sAh[(buf * BM + wm + i * 16) * LD + ks], LD);
                wmma::load_matrix_sync(al[i], &sAl[(buf * BM + wm + i * 16) * LD + ks], LD);
            }
#pragma unroll
            for (int j = 0; j < 4; j++) {
                wmma::load_matrix_sync(bh[j], &sBh[(buf * BN + wn + j * 16) * LD + ks], LD);
                wmma::load_matrix_sync(bl[j], &sBl[(buf * BN + wn + j * 16) * LD + ks], LD);
            }
#pragma unroll
            for (int i = 0; i < 2; i++)
#pragma unroll
                for (int j = 0; j < 4; j++) {
                    wmma::mma_sync(acc[i][j], ah[i], bl[j], acc[i][j]);
                    wmma::mma_sync(acc[i][j], al[i], bh[j], acc[i][j]);
                    wmma::mma_sync(acc[i][j], ah[i], bh[j], acc[i][j]);
                }
        }
        __syncthreads();
        buf ^= 1;
    }

#pragma unroll
    for (int i = 0; i < 2; i++)
#pragma unroll
        for (int j = 0; j < 4; j++) {
#pragma unroll
            for (int e = 0; e < acc[i][j].num_elements; e++)
                acc[i][j].x[e] = wmma::__float_to_tf32(acc[i][j].x[e]);
            wmma::store_matrix_sync(&C[(long)(tm + wm + i * 16) * N + tn + wn + j * 16],
                                    acc[i][j], N, wmma::mem_row_major);
        }
}

// ===========================================================================
// Plain TF32:  C = alpha * A(M,K) * B(N,K)^T.  Pre-rounded inputs.
// 128 threads, 4 warps (2x2), warp tile 64x64 -> 16 MMAs per 8 frag loads.
// 3-stage cp.async pipeline, ONE __syncthreads per k-iter.
// ===========================================================================
__global__ void __launch_bounds__(128, 2) gemm_abT_plain(
    const float* __restrict__ Ab, const float* __restrict__ Bb,
    float* __restrict__ Cb, int N, int K,
    long sA, long sB, long sC, float alpha)
{
    constexpr int BM = 128, BN = 128, BK = 32, LD = BK + 4;
    extern __shared__ float sm[];
    float* As = sm;                    // [3][BM][LD]
    float* Bs = sm + 3 * BM * LD;      // [3][BN][LD]

    const float* A = Ab + (long)blockIdx.z * sA;
    const float* B = Bb + (long)blockIdx.z * sB;
    float*       C = Cb + (long)blockIdx.z * sC;

    const int tm   = blockIdx.y * BM;
    const int tn   = blockIdx.x * BN;
    const int tid  = threadIdx.x;
    const int warp = tid >> 5;
    const int wm   = (warp >> 1) * 64;   // 2x2 warp grid, 64x64 tiles
    const int wn   = (warp & 1) * 64;

    wmma::fragment<wmma::accumulator, 16, 16, 8, float> acc[4][4];
#pragma unroll
    for (int i = 0; i < 4; i++)
#pragma unroll
        for (int j = 0; j < 4; j++) wmma::fill_fragment(acc[i][j], 0.0f);

    // Loader: thread = one row of A and one row of B; 8 x 16B chunks each.
    auto load_tile = [&](int buf, int kk) {
#pragma unroll
        for (int j = 0; j < 8; j++) {
            cp_async16(&As[(buf * BM + tid) * LD + j * 4], &A[(long)(tm + tid) * K + kk + j * 4]);
            cp_async16(&Bs[(buf * BN + tid) * LD + j * 4], &B[(long)(tn + tid) * K + kk + j * 4]);
        }
        cp_commit();
    };

    const int NCH = K / BK;
    load_tile(0, 0);
    load_tile(1, BK);

    int buf = 0;
    for (int c = 0; c < NCH; c++) {
        if (c + 1 < NCH) cp_wait1(); else cp_wait0();
        __syncthreads();

#pragma unroll
        for (int ks = 0; ks < BK; ks += 8) {
            wmma::fragment<wmma::matrix_a, 16, 16, 8, wmma::precision::tf32, wmma::row_major> af[4];
            wmma::fragment<wmma::matrix_b, 16, 16, 8, wmma::precision::tf32, wmma::col_major> bf[4];
#pragma unroll
            for (int i = 0; i < 4; i++)
                wmma::load_matrix_sync(af[i], &As[(buf * BM + wm + i * 16) * LD + ks], LD);
#pragma unroll
            for (int j = 0; j < 4; j++)
                wmma::load_matrix_sync(bf[j], &Bs[(buf * BN + wn + j * 16) * LD + ks], LD);
#pragma unroll
            for (int i = 0; i < 4; i++)
#pragma unroll
                for (int j = 0; j < 4; j++)
                    wmma::mma_sync(acc[i][j], af[i], bf[j], acc[i][j]);
        }

        if (c + 2 < NCH) {
            int nb = buf + 2; if (nb >= 3) nb -= 3;
            load_tile(nb, (c + 2) * BK);
        }
        buf = (buf + 1 == 3) ? 0 : buf + 1;
    }

#pragma unroll
    for (int i = 0; i < 4; i++)
#pragma unroll
        for (int j = 0; j < 4; j++) {
#pragma unroll
            for (int e = 0; e < acc[i][j].num_elements; e++) acc[i][j].x[e] *= alpha;
            wmma::store_matrix_sync(&C[(long)(tm + wm + i * 16) * N + tn + wn + j * 16],
                                    acc[i][j], N, wmma::mem_row_major);
        }
}

// ===========================================================================
// Plain TF32:  C = A(M,K) * B(K,N).  Same 64x64 warp tiling, 3-stage.
// ===========================================================================
__global__ void __launch_bounds__(128, 2) gemm_ab_plain(
    const float* __restrict__ Ab, const float* __restrict__ Bb,
    float* __restrict__ Cb, int N, int K,
    long sA, long sB, long sC)
{
    constexpr int BM = 128, BN = 128, BK = 32, LDA = BK + 4, LDB = BN + 4;
    extern __shared__ float sm[];
    float* As = sm;                    // [3][BM][LDA]
    float* Bs = sm + 3 * BM * LDA;     // [3][BK][LDB]

    const float* A = Ab + (long)blockIdx.z * sA;
    const float* B = Bb + (long)blockIdx.z * sB;
    float*       C = Cb + (long)blockIdx.z * sC;

    const int tm   = blockIdx.y * BM;
    const int tn   = blockIdx.x * BN;
    const int tid  = threadIdx.x;
    const int warp = tid >> 5;
    const int wm   = (warp >> 1) * 64;
    const int wn   = (warp & 1) * 64;

    wmma::fragment<wmma::accumulator, 16, 16, 8, float> acc[4][4];
#pragma unroll
    for (int i = 0; i < 4; i++)
#pragma unroll
        for (int j = 0; j < 4; j++) wmma::fill_fragment(acc[i][j], 0.0f);

    // A loader: row = tid, 8 chunks.  B loader: 32x128 tile, row = tid>>2,
    // chunks (tid&3) + 4k, k = 0..7.
    const int brow = tid >> 2;
    const int bch  = tid & 3;

    auto load_tile = [&](int buf, int kk) {
#pragma unroll
        for (int j = 0; j < 8; j++)
            cp_async16(&As[(buf * BM + tid) * LDA + j * 4], &A[(long)(tm + tid) * K + kk + j * 4]);
#pragma unroll
        for (int j = 0; j < 8; j++) {
            int ch = bch + j * 4;
            cp_async16(&Bs[(buf * BK + brow) * LDB + ch * 4], &B[(long)(kk + brow) * N + tn + ch * 4]);
        }
        cp_commit();
    };

    const int NCH = K / BK;
    load_tile(0, 0);
    load_tile(1, BK);

    int buf = 0;
    for (int c = 0; c < NCH; c++) {
        if (c + 1 < NCH) cp_wait1(); else cp_wait0();
        __syncthreads();

#pragma unroll
        for (int ks = 0; ks < BK; ks += 8) {
            wmma::fragment<wmma::matrix_a, 16, 16, 8, wmma::precision::tf32, wmma::row_major> af[4];
            wmma::fragment<wmma::matrix_b, 16, 16, 8, wmma::precision::tf32, wmma::row_major> bf[4];
#pragma unroll
            for (int i = 0; i < 4; i++)
                wmma::load_matrix_sync(af[i], &As[(buf * BM + wm + i * 16) * LDA + ks], LDA);
#pragma unroll
            for (int j = 0; j < 4; j++)
                wmma::load_matrix_sync(bf[j], &Bs[(buf * BK + ks) * LDB + wn + j * 16], LDB);
#pragma unroll
            for (int i = 0; i < 4; i++)
#pragma unroll
                for (int j = 0; j < 4; j++)
                    wmma::mma_sync(acc[i][j], af[i], bf[j], acc[i][j]);
        }

        if (c + 2 < NCH) {
            int nb = buf + 2; if (nb >= 3) nb -= 3;
            load_tile(nb, (c + 2) * BK);
        }
        buf = (buf + 1 == 3) ? 0 : buf + 1;
    }

#pragma unroll
    for (int i = 0; i < 4; i++)
#pragma unroll
        for (int j = 0; j < 4; j++)
            wmma::store_matrix_sync(&C[(long)(tm + wm + i * 16) * N + tn + wn + j * 16],
                                    acc[i][j], N, wmma::mem_row_major);
}

// ---------------------------------------------------------------------------
// In-place row softmax over 4096-wide rows; exp computed on f16x2 (one MUFU
// op per two elements); output rounded to the tf32 grid.
// ---------------------------------------------------------------------------
__global__ void __launch_bounds__(256) softmax_kernel(float* __restrict__ Sg)
{
    float* row = Sg + (size_t)blockIdx.x * SQ;
    const int tid = threadIdx.x;
    __shared__ float red[8];

    float vals[16];
    float m = -3.4e38f;
#pragma unroll
    for (int i = 0; i < 16; i++) {
        vals[i] = row[tid + i * 256];
        m = fmaxf(m, vals[i]);
    }
#pragma unroll
    for (int o = 16; o; o >>= 1) m = fmaxf(m, __shfl_xor_sync(0xffffffffu, m, o));
    if ((tid & 31) == 0) red[tid >> 5] = m;
    __syncthreads();
    {
        float t = red[tid & 7];
#pragma unroll
        for (int o = 4; o; o >>= 1) t = fmaxf(t, __shfl_xor_sync(0xffffffffu, t, o));
        m = t;
    }

    float sum = 0.0f;
#pragma unroll
    for (int i = 0; i < 8; i++) {
        __half2 x = __floats2half2_rn(vals[2 * i] - m, vals[2 * i + 1] - m);
        float2 e = __half22float2(h2exp(x));
        vals[2 * i]     = e.x;
        vals[2 * i + 1] = e.y;
        sum += e.x + e.y;
    }
#pragma unroll
    for (int o = 16; o; o >>= 1) sum += __shfl_xor_sync(0xffffffffu, sum, o);
    __syncthreads();
    if ((tid & 31) == 0) red[tid >> 5] = sum;
    __syncthreads();
    {
        float t = red[tid & 7];
#pragma unroll
        for (int o = 4; o; o >>= 1) t += __shfl_xor_sync(0xffffffffu, t, o);
        sum = t;
    }

    float inv = 1.0f / sum;
#pragma unroll
    for (int i = 0; i < 16; i++)
        row[tid + i * 256] = wmma::__float_to_tf32(vals[i] * inv);
}

// ---------------------------------------------------------------------------
extern "C" void kernel_launch(void* const* d_in, const int* in_sizes, int n_in,
                              void* d_out, int out_size)
{
    const float* x  = (const float*)d_in[0];
    const float* Wq = (const float*)d_in[1];
    const float* Wk = (const float*)d_in[2];
    const float* Wv = (const float*)d_in[3];
    float* out = (float*)d_out;

    float *q, *k, *v, *s;
    __nv_bfloat16 *xh, *xl, *wh, *wl;
    cudaGetSymbolAddress((void**)&q,  g_q);
    cudaGetSymbolAddress((void**)&k,  g_k);
    cudaGetSymbolAddress((void**)&v,  g_v);
    cudaGetSymbolAddress((void**)&s,  g_s);
    cudaGetSymbolAddress((void**)&xh, g_xh);
    cudaGetSymbolAddress((void**)&xl, g_xl);
    cudaGetSymbolAddress((void**)&wh, g_wh);
    cudaGetSymbolAddress((void**)&wl, g_wl);

    const int smem_abT  = 3 * (128 * 36 + 128 * 36) * 4;            // 110592
    const int smem_ab   = 3 * (128 * 36 * 4 + 32 * 132 * 4);        // 105984
    const int smem_qkv  = 2 * 4 * 128 * 48 * 2;                     // 98304

    cudaFuncSetAttribute(gemm_abT_plain, cudaFuncAttributeMaxDynamicSharedMemorySize, smem_abT);
    cudaFuncSetAttribute(gemm_ab_plain,  cudaFuncAttributeMaxDynamicSharedMemorySize, smem_ab);
    cudaFuncSetAttribute(gemm_qkv_bf16,  cudaFuncAttributeMaxDynamicSharedMemorySize, smem_qkv);

    const int nx = NB * SQ * DM;
    const int nw = DM * DM;

    // Phase 0: hi/lo bf16 splits.
    split_bf16<<<nx / 4 / 256, 256>>>(x,  xh, xl, nx);
    split_bf16<<<nw / 4 / 256, 256>>>(Wq, wh + 0L * nw, wl + 0L * nw, nw);
    split_bf16<<<nw / 4 / 256, 256>>>(Wk, wh + 1L * nw, wl + 1L * nw, nw);
    split_bf16<<<nw / 4 / 256, 256>>>(Wv, wh + 2L * nw, wl + 2L * nw, nw);

    // Phase 1: QKV projections (3-term bf16), outputs tf32-rounded.
    {
        dim3 grid(DM / 128, (NB * SQ) / 128, 1);
        gemm_qkv_bf16<<<grid, 256, smem_qkv>>>(xh, xl, wh + 0L * nw, wl + 0L * nw, q, DM, DM);
        gemm_qkv_bf16<<<grid, 256, smem_qkv>>>(xh, xl, wh + 1L * nw, wl + 1L * nw, k, DM, DM);
        gemm_qkv_bf16<<<grid, 256, smem_qkv>>>(xh, xl, wh + 2L * nw, wl + 2L * nw, v, DM, DM);
    }

    // Phase 2: scores = (Q K^T) / 32, batched.
    {
        dim3 grid(SQ / 128, SQ / 128, NB);
        gemm_abT_plain<<<grid, 128, smem_abT>>>(q, k, s, SQ, DM,
                                                (long)SQ * DM, (long)SQ * DM,
                                                (long)SQ * SQ, 1.0f / 32.0f);
    }

    // Phase 3: row softmax (in place), f16x2 exp, tf32-rounded output.
    softmax_kernel<<<NB * SQ, 256>>>(s);

    // Phase 4: out = P V, batched.
    {
        dim3 grid(DM / 128, SQ / 128, NB);
        gemm_ab_plain<<<grid, 128, smem_ab>>>(s, v, out, DM, SQ,
                                              (long)SQ * SQ, (long)SQ * DM,
                                              (long)SQ * DM);
    }
}

// round 13
// speedup vs baseline: 2.3510x; 2.3510x over previous
#include <cuda_runtime.h>
#include <cstdint>
#include <mma.h>
#include <math.h>
#include <cuda_bf16.h>
#include <cuda_fp16.h>

using namespace nvcuda;

#define DM   1024
#define NB   4
#define SQ   4096

// Scratch (device globals: the sanctioned alloc-free workaround)
__device__ float g_q[(size_t)NB * SQ * DM];
__device__ float g_k[(size_t)NB * SQ * DM];
__device__ float g_v[(size_t)NB * SQ * DM];
__device__ float g_s[(size_t)NB * SQ * SQ];
__device__ __half g_qh[(size_t)NB * SQ * DM];
__device__ __half g_kh[(size_t)NB * SQ * DM];
__device__ __half g_vh[(size_t)NB * SQ * DM];
__device__ __half g_p [(size_t)NB * SQ * SQ];
__device__ __nv_bfloat16 g_xh[(size_t)NB * SQ * DM];
__device__ __nv_bfloat16 g_xl[(size_t)NB * SQ * DM];
__device__ __nv_bfloat16 g_wh[3][(size_t)DM * DM];
__device__ __nv_bfloat16 g_wl[3][(size_t)DM * DM];

__device__ __forceinline__ void cp_async16(void* dst_smem, const void* src_gmem)
{
    uint32_t d = (uint32_t)__cvta_generic_to_shared(dst_smem);
    asm volatile("cp.async.cg.shared.global [%0], [%1], 16;\n" :: "r"(d), "l"(src_gmem));
}
__device__ __forceinline__ void cp_commit() { asm volatile("cp.async.commit_group;\n" ::); }
__device__ __forceinline__ void cp_wait0()  { asm volatile("cp.async.wait_group 0;\n" ::); }
__device__ __forceinline__ void cp_wait1()  { asm volatile("cp.async.wait_group 1;\n" ::); }

// ===========================================================================
// Elementwise split: fp32 -> bf16 hi + bf16 lo.
// ===========================================================================
__global__ void __launch_bounds__(256) split_bf16(
    const float* __restrict__ in, __nv_bfloat16* __restrict__ h,
    __nv_bfloat16* __restrict__ l, int n)
{
    int idx = (blockIdx.x * 256 + threadIdx.x) * 4;
    if (idx >= n) return;
    float4 v = *(const float4*)&in[idx];
    __nv_bfloat16 h0 = __float2bfloat16_rn(v.x);
    __nv_bfloat16 h1 = __float2bfloat16_rn(v.y);
    __nv_bfloat16 h2 = __float2bfloat16_rn(v.z);
    __nv_bfloat16 h3 = __float2bfloat16_rn(v.w);
    __nv_bfloat16 l0 = __float2bfloat16_rn(v.x - __bfloat162float(h0));
    __nv_bfloat16 l1 = __float2bfloat16_rn(v.y - __bfloat162float(h1));
    __nv_bfloat16 l2 = __float2bfloat16_rn(v.z - __bfloat162float(h2));
    __nv_bfloat16 l3 = __float2bfloat16_rn(v.w - __bfloat162float(h3));
    ushort4 hv = { __bfloat16_as_ushort(h0), __bfloat16_as_ushort(h1),
                   __bfloat16_as_ushort(h2), __bfloat16_as_ushort(h3) };
    ushort4 lv = { __bfloat16_as_ushort(l0), __bfloat16_as_ushort(l1),
                   __bfloat16_as_ushort(l2), __bfloat16_as_ushort(l3) };
    *(ushort4*)&h[idx] = hv;
    *(ushort4*)&l[idx] = lv;
}

// ===========================================================================
// Elementwise convert fp32 -> fp16 (RN).
// ===========================================================================
__global__ void __launch_bounds__(256) cvt_f16(
    const float* __restrict__ in, __half* __restrict__ out, int n)
{
    int idx = (blockIdx.x * 256 + threadIdx.x) * 4;
    if (idx >= n) return;
    float4 v = *(const float4*)&in[idx];
    ushort4 o = { __half_as_ushort(__float2half_rn(v.x)),
                  __half_as_ushort(__float2half_rn(v.y)),
                  __half_as_ushort(__float2half_rn(v.z)),
                  __half_as_ushort(__float2half_rn(v.w)) };
    *(ushort4*)&out[idx] = o;
}

// ===========================================================================
// QKV: C(M,N) = (Ah+Al)(M,K) x (Bh+Bl)(N,K)^T, bf16 3-term, fp32 accum/out.
// 2-stage cp.async (round-8/10 proven config).
// ===========================================================================
__global__ void __launch_bounds__(256, 2) gemm_qkv_bf16(
    const __nv_bfloat16* __restrict__ Ah, const __nv_bfloat16* __restrict__ Al,
    const __nv_bfloat16* __restrict__ Bh, const __nv_bfloat16* __restrict__ Bl,
    float* __restrict__ C, int N, int K)
{
    constexpr int BM = 128, BN = 128, BK = 32, LD = BK + 16;
    extern __shared__ __align__(16) char smraw[];
    __nv_bfloat16* sAh = (__nv_bfloat16*)smraw;
    __nv_bfloat16* sAl = sAh + 2 * BM * LD;
    __nv_bfloat16* sBh = sAl + 2 * BM * LD;
    __nv_bfloat16* sBl = sBh + 2 * BN * LD;

    const int tm   = blockIdx.y * BM;
    const int tn   = blockIdx.x * BN;
    const int tid  = threadIdx.x;
    const int warp = tid >> 5;
    const int wm   = (warp >> 1) * 32;
    const int wn   = (warp & 1) * 64;

    wmma::fragment<wmma::accumulator, 16, 16, 16, float> acc[2][4];
#pragma unroll
    for (int i = 0; i < 2; i++)
#pragma unroll
        for (int j = 0; j < 4; j++) wmma::fill_fragment(acc[i][j], 0.0f);

    const int lr = tid >> 1;
    const int lc = (tid & 1) * 16;

    auto load_tile = [&](int buf, int kk) {
        long ga = (long)(tm + lr) * K + kk + lc;
        long gb = (long)(tn + lr) * K + kk + lc;
        int  sa = (buf * BM + lr) * LD + lc;
        int  sb = (buf * BN + lr) * LD + lc;
        cp_async16(&sAh[sa],     &Ah[ga]);
        cp_async16(&sAh[sa + 8], &Ah[ga + 8]);
        cp_async16(&sAl[sa],     &Al[ga]);
        cp_async16(&sAl[sa + 8], &Al[ga + 8]);
        cp_async16(&sBh[sb],     &Bh[gb]);
        cp_async16(&sBh[sb + 8], &Bh[gb + 8]);
        cp_async16(&sBl[sb],     &Bl[gb]);
        cp_async16(&sBl[sb + 8], &Bl[gb + 8]);
        cp_commit();
    };

    load_tile(0, 0);
    int buf = 0;
    for (int kk = 0; kk < K; kk += BK) {
        const bool has_next = (kk + BK) < K;
        if (has_next) {
            load_tile(buf ^ 1, kk + BK);
            cp_wait1();
        } else {
            cp_wait0();
        }
        __syncthreads();

#pragma unroll
        for (int ks = 0; ks < BK; ks += 16) {
            wmma::fragment<wmma::matrix_a, 16, 16, 16, __nv_bfloat16, wmma::row_major> ah[2], al[2];
            wmma::fragment<wmma::matrix_b, 16, 16, 16, __nv_bfloat16, wmma::col_major> bh[4], bl[4];
#pragma unroll
            for (int i = 0; i < 2; i++) {
                wmma::load_matrix_sync(ah[i], &sAh[(buf * BM + wm + i * 16) * LD + ks], LD);
                wmma::load_matrix_sync(al[i], &sAl[(buf * BM + wm + i * 16) * LD + ks], LD);
            }
#pragma unroll
            for (int j = 0; j < 4; j++) {
                wmma::load_matrix_sync(bh[j], &sBh[(buf * BN + wn + j * 16) * LD + ks], LD);
                wmma::load_matrix_sync(bl[j], &sBl[(buf * BN + wn + j * 16) * LD + ks], LD);
            }
#pragma unroll
            for (int i = 0; i < 2; i++)
#pragma unroll
                for (int j = 0; j < 4; j++) {
                    wmma::mma_sync(acc[i][j], ah[i], bl[j], acc[i][j]);
                    wmma::mma_sync(acc[i][j], al[i], bh[j], acc[i][j]);
                    wmma::mma_sync(acc[i][j], ah[i], bh[j], acc[i][j]);
                }
        }
        __syncthreads();
        buf ^= 1;
    }

#pragma unroll
    for (int i = 0; i < 2; i++)
#pragma unroll
        for (int j = 0; j < 4; j++)
            wmma::store_matrix_sync(&C[(long)(tm + wm + i * 16) * N + tn + wn + j * 16],
                                    acc[i][j], N, wmma::mem_row_major);
}

// ===========================================================================
// FP16:  C = alpha * A(M,K) * B(N,K)^T, fp32 accum/out.
// 256 threads (8 warps 4x2, warp 32x64), BK=64, 3-stage one-sync pipeline.
// ===========================================================================
__global__ void __launch_bounds__(256, 2) gemm_abT_f16(
    const __half* __restrict__ Ab, const __half* __restrict__ Bb,
    float* __restrict__ Cb, int N, int K,
    long sA, long sB, long sC, float alpha)
{
    constexpr int BM = 128, BN = 128, BK = 64, LD = BK + 8;
    extern __shared__ __align__(16) char smraw[];
    __half* As = (__half*)smraw;       // [3][BM][LD]
    __half* Bs = As + 3 * BM * LD;     // [3][BN][LD]

    const __half* A = Ab + (long)blockIdx.z * sA;
    const __half* B = Bb + (long)blockIdx.z * sB;
    float*        C = Cb + (long)blockIdx.z * sC;

    const int tm   = blockIdx.y * BM;
    const int tn   = blockIdx.x * BN;
    const int tid  = threadIdx.x;
    const int warp = tid >> 5;
    const int wm   = (warp >> 1) * 32;
    const int wn   = (warp & 1) * 64;

    wmma::fragment<wmma::accumulator, 16, 16, 16, float> acc[2][4];
#pragma unroll
    for (int i = 0; i < 2; i++)
#pragma unroll
        for (int j = 0; j < 4; j++) wmma::fill_fragment(acc[i][j], 0.0f);

    const int lr = tid >> 1;           // 0..127 row
    const int lc = (tid & 1) * 32;     // half-element offset

    auto load_tile = [&](int buf, int kk) {
        long ga = (long)(tm + lr) * K + kk + lc;
        long gb = (long)(tn + lr) * K + kk + lc;
        int  sa = (buf * BM + lr) * LD + lc;
        int  sb = (buf * BN + lr) * LD + lc;
#pragma unroll
        for (int j = 0; j < 4; j++) {
            cp_async16(&As[sa + j * 8], &A[ga + j * 8]);
            cp_async16(&Bs[sb + j * 8], &B[gb + j * 8]);
        }
        cp_commit();
    };

    const int NCH = K / BK;
    load_tile(0, 0);
    load_tile(1, BK);

    int buf = 0;
    for (int c = 0; c < NCH; c++) {
        if (c + 1 < NCH) cp_wait1(); else cp_wait0();
        __syncthreads();

#pragma unroll
        for (int ks = 0; ks < BK; ks += 16) {
            wmma::fragment<wmma::matrix_a, 16, 16, 16, __half, wmma::row_major> af[2];
            wmma::fragment<wmma::matrix_b, 16, 16, 16, __half, wmma::col_major> bf[4];
#pragma unroll
            for (int i = 0; i < 2; i++)
                wmma::load_matrix_sync(af[i], &As[(buf * BM + wm + i * 16) * LD + ks], LD);
#pragma unroll
            for (int j = 0; j < 4; j++)
                wmma::load_matrix_sync(bf[j], &Bs[(buf * BN + wn + j * 16) * LD + ks], LD);
#pragma unroll
            for (int i = 0; i < 2; i++)
#pragma unroll
                for (int j = 0; j < 4; j++)
                    wmma::mma_sync(acc[i][j], af[i], bf[j], acc[i][j]);
        }

        if (c + 2 < NCH) {
            int nb = buf + 2; if (nb >= 3) nb -= 3;
            load_tile(nb, (c + 2) * BK);
        }
        buf = (buf + 1 == 3) ? 0 : buf + 1;
    }

#pragma unroll
    for (int i = 0; i < 2; i++)
#pragma unroll
        for (int j = 0; j < 4; j++) {
#pragma unroll
            for (int e = 0; e < acc[i][j].num_elements; e++) acc[i][j].x[e] *= alpha;
            wmma::store_matrix_sync(&C[(long)(tm + wm + i * 16) * N + tn + wn + j * 16],
                                    acc[i][j], N, wmma::mem_row_major);
        }
}

// ===========================================================================
// FP16:  C = A(M,K) * B(K,N), fp32 accum/out. Same pipeline; B tile 64x128.
// ===========================================================================
__global__ void __launch_bounds__(256, 2) gemm_ab_f16(
    const __half* __restrict__ Ab, const __half* __restrict__ Bb,
    float* __restrict__ Cb, int N, int K,
    long sA, long sB, long sC)
{
    constexpr int BM = 128, BN = 128, BK = 64, LDA = BK + 8, LDB = BN + 8;
    extern __shared__ __align__(16) char smraw[];
    __half* As = (__half*)smraw;        // [3][BM][LDA]
    __half* Bs = As + 3 * BM * LDA;     // [3][BK][LDB]

    const __half* A = Ab + (long)blockIdx.z * sA;
    const __half* B = Bb + (long)blockIdx.z * sB;
    float*        C = Cb + (long)blockIdx.z * sC;

    const int tm   = blockIdx.y * BM;
    const int tn   = blockIdx.x * BN;
    const int tid  = threadIdx.x;
    const int warp = tid >> 5;
    const int wm   = (warp >> 1) * 32;
    const int wn   = (warp & 1) * 64;

    wmma::fragment<wmma::accumulator, 16, 16, 16, float> acc[2][4];
#pragma unroll
    for (int i = 0; i < 2; i++)
#pragma unroll
        for (int j = 0; j < 4; j++) wmma::fill_fragment(acc[i][j], 0.0f);

    const int ar = tid >> 1;           // A: 0..127 row, 4 chunks each
    const int ac = (tid & 1) * 32;
    const int br = tid >> 2;           // B: 0..63 row, 4 chunks each
    const int bc = tid & 3;            // chunk group

    auto load_tile = [&](int buf, int kk) {
        long ga = (long)(tm + ar) * K + kk + ac;
        int  sa = (buf * BM + ar) * LDA + ac;
#pragma unroll
        for (int j = 0; j < 4; j++)
            cp_async16(&As[sa + j * 8], &A[ga + j * 8]);
        long gb = (long)(kk + br) * N + tn;
        int  sb = (buf * BK + br) * LDB;
#pragma unroll
        for (int j = 0; j < 4; j++) {
            int ch = bc + j * 4;       // 0..15
            cp_async16(&Bs[sb + ch * 8], &B[gb + ch * 8]);
        }
        cp_commit();
    };

    const int NCH = K / BK;
    load_tile(0, 0);
    load_tile(1, BK);

    int buf = 0;
    for (int c = 0; c < NCH; c++) {
        if (c + 1 < NCH) cp_wait1(); else cp_wait0();
        __syncthreads();

#pragma unroll
        for (int ks = 0; ks < BK; ks += 16) {
            wmma::fragment<wmma::matrix_a, 16, 16, 16, __half, wmma::row_major> af[2];
            wmma::fragment<wmma::matrix_b, 16, 16, 16, __half, wmma::row_major> bf[4];
#pragma unroll
            for (int i = 0; i < 2; i++)
                wmma::load_matrix_sync(af[i], &As[(buf * BM + wm + i * 16) * LDA + ks], LDA);
#pragma unroll
            for (int j = 0; j < 4; j++)
                wmma::load_matrix_sync(bf[j], &Bs[(buf * BK + ks) * LDB + wn + j * 16], LDB);
#pragma unroll
            for (int i = 0; i < 2; i++)
#pragma unroll
                for (int j = 0; j < 4; j++)
                    wmma::mma_sync(acc[i][j], af[i], bf[j], acc[i][j]);
        }

        if (c + 2 < NCH) {
            int nb = buf + 2; if (nb >= 3) nb -= 3;
            load_tile(nb, (c + 2) * BK);
        }
        buf = (buf + 1 == 3) ? 0 : buf + 1;
    }

#pragma unroll
    for (int i = 0; i < 2; i++)
#pragma unroll
        for (int j = 0; j < 4; j++)
            wmma::store_matrix_sync(&C[(long)(tm + wm + i * 16) * N + tn + wn + j * 16],
                                    acc[i][j], N, wmma::mem_row_major);
}

// ---------------------------------------------------------------------------
// Row softmax over 4096-wide rows; f16x2 exp; writes fp16 probabilities.
// ---------------------------------------------------------------------------
__global__ void __launch_bounds__(256) softmax_f16(
    const float* __restrict__ Sg, __half* __restrict__ P)
{
    const float* row = Sg + (size_t)blockIdx.x * SQ;
    __half* prow = P + (size_t)blockIdx.x * SQ;
    const int tid = threadIdx.x;
    __shared__ float red[8];

    float vals[16];
    float m = -3.4e38f;
#pragma unroll
    for (int i = 0; i < 16; i++) {
        vals[i] = row[tid + i * 256];
        m = fmaxf(m, vals[i]);
    }
#pragma unroll
    for (int o = 16; o; o >>= 1) m = fmaxf(m, __shfl_xor_sync(0xffffffffu, m, o));
    if ((tid & 31) == 0) red[tid >> 5] = m;
    __syncthreads();
    {
        float t = red[tid & 7];
#pragma unroll
        for (int o = 4; o; o >>= 1) t = fmaxf(t, __shfl_xor_sync(0xffffffffu, t, o));
        m = t;
    }

    float sum = 0.0f;
#pragma unroll
    for (int i = 0; i < 8; i++) {
        __half2 x = __floats2half2_rn(vals[2 * i] - m, vals[2 * i + 1] - m);
        float2 e = __half22float2(h2exp(x));
        vals[2 * i]     = e.x;
        vals[2 * i + 1] = e.y;
        sum += e.x + e.y;
    }
#pragma unroll
    for (int o = 16; o; o >>= 1) sum += __shfl_xor_sync(0xffffffffu, sum, o);
    __syncthreads();
    if ((tid & 31) == 0) red[tid >> 5] = sum;
    __syncthreads();
    {
        float t = red[tid & 7];
#pragma unroll
        for (int o = 4; o; o >>= 1) t += __shfl_xor_sync(0xffffffffu, t, o);
        sum = t;
    }

    float inv = 1.0f / sum;
#pragma unroll
    for (int i = 0; i < 8; i++) {
        __half2 p2 = __floats2half2_rn(vals[2 * i] * inv, vals[2 * i + 1] * inv);
        *(__half2*)&prow[tid * 2 + i * 512] = p2;   // pairs: layout tid interleaved
    }
}

// NOTE on softmax output layout: thread tid handles elements {tid + i*256}.
// Writing pairs (2*tid + i*512) would permute data. Use scalar stores at the
// original indices instead (correctness over micro-optimization).
__global__ void __launch_bounds__(256) softmax_f16_safe(
    const float* __restrict__ Sg, __half* __restrict__ P)
{
    const float* row = Sg + (size_t)blockIdx.x * SQ;
    __half* prow = P + (size_t)blockIdx.x * SQ;
    const int tid = threadIdx.x;
    __shared__ float red[8];

    float vals[16];
    float m = -3.4e38f;
#pragma unroll
    for (int i = 0; i < 16; i++) {
        vals[i] = row[tid + i * 256];
        m = fmaxf(m, vals[i]);
    }
#pragma unroll
    for (int o = 16; o; o >>= 1) m = fmaxf(m, __shfl_xor_sync(0xffffffffu, m, o));
    if ((tid & 31) == 0) red[tid >> 5] = m;
    __syncthreads();
    {
        float t = red[tid & 7];
#pragma unroll
        for (int o = 4; o; o >>= 1) t = fmaxf(t, __shfl_xor_sync(0xffffffffu, t, o));
        m = t;
    }

    float sum = 0.0f;
#pragma unroll
    for (int i = 0; i < 8; i++) {
        __half2 x = __floats2half2_rn(vals[2 * i] - m, vals[2 * i + 1] - m);
        float2 e = __half22float2(h2exp(x));
        vals[2 * i]     = e.x;
        vals[2 * i + 1] = e.y;
        sum += e.x + e.y;
    }
#pragma unroll
    for (int o = 16; o; o >>= 1) sum += __shfl_xor_sync(0xffffffffu, sum, o);
    __syncthreads();
    if ((tid & 31) == 0) red[tid >> 5] = sum;
    __syncthreads();
    {
        float t = red[tid & 7];
#pragma unroll
        for (int o = 4; o; o >>= 1) t += __shfl_xor_sync(0xffffffffu, t, o);
        sum = t;
    }

    float inv = 1.0f / sum;
#pragma unroll
    for (int i = 0; i < 16; i++)
        prow[tid + i * 256] = __float2half_rn(vals[i] * inv);
}

// ---------------------------------------------------------------------------
extern "C" void kernel_launch(void* const* d_in, const int* in_sizes, int n_in,
                              void* d_out, int out_size)
{
    const float* x  = (const float*)d_in[0];
    const float* Wq = (const float*)d_in[1];
    const float* Wk = (const float*)d_in[2];
    const float* Wv = (const float*)d_in[3];
    float* out = (float*)d_out;

    float *q, *k, *v, *s;
    __half *qh, *kh, *vh, *p;
    __nv_bfloat16 *xh, *xl, *wh, *wl;
    cudaGetSymbolAddress((void**)&q,  g_q);
    cudaGetSymbolAddress((void**)&k,  g_k);
    cudaGetSymbolAddress((void**)&v,  g_v);
    cudaGetSymbolAddress((void**)&s,  g_s);
    cudaGetSymbolAddress((void**)&qh, g_qh);
    cudaGetSymbolAddress((void**)&kh, g_kh);
    cudaGetSymbolAddress((void**)&vh, g_vh);
    cudaGetSymbolAddress((void**)&p,  g_p);
    cudaGetSymbolAddress((void**)&xh, g_xh);
    cudaGetSymbolAddress((void**)&xl, g_xl);
    cudaGetSymbolAddress((void**)&wh, g_wh);
    cudaGetSymbolAddress((void**)&wl, g_wl);

    const int smem_qkv = 2 * 4 * 128 * 48 * 2;                       // 98304
    const int smem_abT = 3 * 2 * 128 * 72 * 2;                       // 110592
    const int smem_ab  = 3 * (128 * 72 + 64 * 136) * 2;              // 107520

    cudaFuncSetAttribute(gemm_qkv_bf16, cudaFuncAttributeMaxDynamicSharedMemorySize, smem_qkv);
    cudaFuncSetAttribute(gemm_abT_f16,  cudaFuncAttributeMaxDynamicSharedMemorySize, smem_abT);
    cudaFuncSetAttribute(gemm_ab_f16,   cudaFuncAttributeMaxDynamicSharedMemorySize, smem_ab);

    const int nx = NB * SQ * DM;
    const int nw = DM * DM;

    // Phase 0: hi/lo bf16 splits of inputs.
    split_bf16<<<nx / 4 / 256, 256>>>(x,  xh, xl, nx);
    split_bf16<<<nw / 4 / 256, 256>>>(Wq, wh + 0L * nw, wl + 0L * nw, nw);
    split_bf16<<<nw / 4 / 256, 256>>>(Wk, wh + 1L * nw, wl + 1L * nw, nw);
    split_bf16<<<nw / 4 / 256, 256>>>(Wv, wh + 2L * nw, wl + 2L * nw, nw);

    // Phase 1: QKV projections (3-term bf16), fp32 out.
    {
        dim3 grid(DM / 128, (NB * SQ) / 128, 1);
        gemm_qkv_bf16<<<grid, 256, smem_qkv>>>(xh, xl, wh + 0L * nw, wl + 0L * nw, q, DM, DM);
        gemm_qkv_bf16<<<grid, 256, smem_qkv>>>(xh, xl, wh + 1L * nw, wl + 1L * nw, k, DM, DM);
        gemm_qkv_bf16<<<grid, 256, smem_qkv>>>(xh, xl, wh + 2L * nw, wl + 2L * nw, v, DM, DM);
    }

    // Phase 1b: round Q,K,V to fp16.
    cvt_f16<<<nx / 4 / 256, 256>>>(q, qh, nx);
    cvt_f16<<<nx / 4 / 256, 256>>>(k, kh, nx);
    cvt_f16<<<nx / 4 / 256, 256>>>(v, vh, nx);

    // Phase 2: scores = (Q K^T) / 32, fp16 inputs, fp32 out.
    {
        dim3 grid(SQ / 128, SQ / 128, NB);
        gemm_abT_f16<<<grid, 256, smem_abT>>>(qh, kh, s, SQ, DM,
                                              (long)SQ * DM, (long)SQ * DM,
                                              (long)SQ * SQ, 1.0f / 32.0f);
    }

    // Phase 3: softmax -> fp16 P.
    softmax_f16_safe<<<NB * SQ, 256>>>(s, p);

    // Phase 4: out = P V, fp16 inputs, fp32 out.
    {
        dim3 grid(DM / 128, SQ / 128, NB);
        gemm_ab_f16<<<grid, 256, smem_ab>>>(p, vh, out, DM, SQ,
                                            (long)SQ * SQ, (long)SQ * DM,
                                            (long)SQ * DM);
    }
}